// round 13
// baseline (speedup 1.0000x reference)
#include <cuda_runtime.h>
#include <cuda_fp16.h>
#include <math.h>
#include <stdint.h>

// ---------------------------------------------------------------------------
// MMD^2 (RBF, gamma=1), 8192x16 fp32, via mma.sync.m16n8k16 fp16 (sm_100 base).
//
// Coords scaled by sqrt(2*log2e), split x = hi + lo (fp16).
// K = 48: A chunks [hi | lo | hi], B chunks [hi | hi | lo]
//   => acc = 2*log2e*dot(a,b)  (lo*lo dropped, ~2^-22 rel)
// Epilogue: k = ex2(acc) * ena * enb, ena/enb = exp2(-0.5|x_s|^2) per row.
// CTA = 256 threads, output tile 128(m) x 64(n); warp tile 16m x 64n
// (acc 32 regs, A-frags 12 regs -> fits 3 CTAs/SM = 37.5% occupancy).
// Final reduction fused into the last CTA (threadfence-reduction pattern).
// ---------------------------------------------------------------------------

#define NSRC   8192
#define D      16
#define NP     16384
#define TILE   128
#define TB     (NP / TILE)                 // 128
#define NTRI   (TB * (TB + 1) / 2)         // 8256 triangle tiles
#define NBLK   (NTRI * 2)                  // 16512 CTAs (two n-halves)
#define SQ2L   1.6986436004918308f         // sqrt(2*log2(e))
#define ROWB   112                         // 96B data + 16B pad (conflict-free)
#define NKC    3                           // K = 48, chunks of 16
#define ATILEB (TILE * ROWB)               // 14336 B (A: 128 rows)
#define BTILEB (64 * ROWB)                 // 7168 B  (B: 64 rows)

// per point: u0,u1 = hi(16 fp16), u2,u3 = lo
__device__ uint4  g_S[NP * 4];
__device__ float  g_N[NP];                 // -0.5*|x_s|^2
__device__ double g_part[NBLK];
__device__ unsigned int g_count;

// ---------------- helpers ----------------
__device__ __forceinline__ float ex2(float x) {
    float r; asm("ex2.approx.f32 %0, %1;" : "=f"(r) : "f"(x)); return r;
}
__device__ __forceinline__ uint32_t smem_u32(const void* p) {
    uint32_t a;
    asm("{ .reg .u64 t; cvta.to.shared.u64 t, %1; cvt.u32.u64 %0, t; }"
        : "=r"(a) : "l"(p));
    return a;
}
__device__ __forceinline__ void ldsm4(uint32_t* r, uint32_t addr) {
    asm volatile("ldmatrix.sync.aligned.m8n8.x4.shared.b16 {%0,%1,%2,%3}, [%4];"
                 : "=r"(r[0]), "=r"(r[1]), "=r"(r[2]), "=r"(r[3]) : "r"(addr));
}
__device__ __forceinline__ void mma16816(float* c, const uint32_t* a,
                                         uint32_t b0, uint32_t b1) {
    asm volatile("mma.sync.aligned.m16n8k16.row.col.f32.f16.f16.f32 "
                 "{%0,%1,%2,%3}, {%4,%5,%6,%7}, {%8,%9}, {%0,%1,%2,%3};"
                 : "+f"(c[0]), "+f"(c[1]), "+f"(c[2]), "+f"(c[3])
                 : "r"(a[0]), "r"(a[1]), "r"(a[2]), "r"(a[3]), "r"(b0), "r"(b1));
}
__device__ __forceinline__ int tri_row_start(int t) {
    return t * TB - ((t * (t - 1)) >> 1);
}

// ---------------------------------------------------------------------------
// Kernel 1: scale, fp16 hi/lo split, norm term. Also resets g_count.
// ---------------------------------------------------------------------------
__global__ void __launch_bounds__(128) split_kernel(const float* __restrict__ src,
                                                    const float* __restrict__ tgt) {
    if (blockIdx.x == 0 && threadIdx.x == 0) g_count = 0u;
    int p = blockIdx.x * 128 + threadIdx.x;
    if (p >= NP) return;
    const float* x = (p < NSRC) ? (src + (size_t)p * D) : (tgt + (size_t)(p - NSRC) * D);

    uint4 u[4];
    __half* hi = (__half*)&u[0];
    __half* lo = (__half*)&u[2];

    float ns = 0.f;
#pragma unroll
    for (int d = 0; d < D; d++) {
        float v = x[d] * SQ2L;
        ns = fmaf(v, v, ns);
        __half h = __float2half_rn(v);
        hi[d] = h;
        lo[d] = __float2half_rn(v - __half2float(h));
    }
    uint4* out = g_S + (size_t)p * 4;
#pragma unroll
    for (int i = 0; i < 4; i++) out[i] = u[i];
    g_N[p] = -0.5f * ns;
}

// ---------------------------------------------------------------------------
// Kernel 2: 128x64 output tile per CTA (256 threads, 8 warps).
// Warp w: rows w*16 + {0..15}, all 64 n-cols (8 n8-tiles).
// ---------------------------------------------------------------------------
__global__ void __launch_bounds__(256, 3) pair_kernel(float* __restrict__ out) {
    extern __shared__ __align__(16) char dsm[];
    __shared__ float  sLA[TILE];
    __shared__ float  sLB[64];
    __shared__ float  wsum[8];
    __shared__ double sred[256];
    __shared__ unsigned int s_rank;

    const int bid  = blockIdx.x;
    const int tid  = threadIdx.x;
    const int lane = tid & 31;
    const int w    = tid >> 5;

    const int tri   = bid >> 1;
    const int nhalf = bid & 1;

    int ti = (int)((2.0 * TB + 1.0 - sqrt((2.0 * TB + 1.0) * (2.0 * TB + 1.0)
                                          - 8.0 * (double)tri)) * 0.5);
    while (tri_row_start(ti + 1) <= tri) ti++;
    while (tri_row_start(ti) > tri) ti--;
    const int tj = ti + (tri - tri_row_start(ti));

    // ---- build A (128 rows) and B (64 rows) tiles in SMEM ----
    if (tid < 128) {
        const int pa = ti * TILE + tid;
        const uint4* sra = g_S + (size_t)pa * 4;
        char* rba = dsm + tid * ROWB;
        uint4 ua[4];
#pragma unroll
        for (int i = 0; i < 4; i++) ua[i] = sra[i];
        // A: [hi hi lo lo hi hi]
        const int mapA[6] = {0,1, 2,3, 0,1};
#pragma unroll
        for (int c = 0; c < 6; c++)
            *(uint4*)(rba + c * 16) = ua[mapA[c]];
        sLA[tid] = ex2(g_N[pa]);
    } else if (tid < 192) {
        const int r  = tid - 128;
        const int pb = tj * TILE + nhalf * 64 + r;
        const uint4* srb = g_S + (size_t)pb * 4;
        char* rbb = dsm + ATILEB + r * ROWB;
        uint4 ub[4];
#pragma unroll
        for (int i = 0; i < 4; i++) ub[i] = srb[i];
        // B: [hi hi hi hi lo lo]
        const int mapB[6] = {0,1, 0,1, 2,3};
#pragma unroll
        for (int c = 0; c < 6; c++)
            *(uint4*)(rbb + c * 16) = ub[mapB[c]];
        sLB[r] = ex2(g_N[pb]);
    }
    __syncthreads();

    const uint32_t sA = smem_u32(dsm);
    const uint32_t sB = sA + ATILEB;
    const int mbase = w * 16;
    const int gid = lane >> 2;
    const int tig = lane & 3;

    // ---- preload A fragments (3 kc x 1 m16 = 12 regs) ----
    const uint32_t aRow   = (uint32_t)(mbase + (lane & 7) + ((lane >> 3) & 1) * 8);
    const uint32_t aAddr  = sA + aRow * ROWB + ((lane >> 4) & 1) * 16;
    uint32_t a[NKC][4];
#pragma unroll
    for (int kc = 0; kc < NKC; kc++) ldsm4(a[kc], aAddr + kc * 32);

    const uint32_t bRowQ = (uint32_t)((lane & 7) + ((lane >> 4) & 1) * 8);
    const uint32_t bColH = ((lane >> 3) & 1) * 16;
    uint32_t bAddr[4];
#pragma unroll
    for (int q = 0; q < 4; q++)
        bAddr[q] = sB + (uint32_t)(16 * q + bRowQ) * ROWB + bColH;

    float acc[8][4];
#pragma unroll
    for (int nt = 0; nt < 8; nt++)
#pragma unroll
        for (int e = 0; e < 4; e++) acc[nt][e] = 0.f;

#pragma unroll
    for (int kc = 0; kc < NKC; kc++) {
        const uint32_t ko = kc * 32;
        uint32_t b[4][4];
#pragma unroll
        for (int q = 0; q < 4; q++) ldsm4(b[q], bAddr[q] + ko);
#pragma unroll
        for (int nt = 0; nt < 8; nt++) {
            const uint32_t b0 = b[nt >> 1][(nt & 1) * 2];
            const uint32_t b1 = b[nt >> 1][(nt & 1) * 2 + 1];
            mma16816(acc[nt], a[kc], b0, b1);
        }
    }

    // ---- epilogue: k = ex2(acc) * ena * enb; sum over tile ----
    float enb[8][2];
#pragma unroll
    for (int nt = 0; nt < 8; nt++) {
        int j0 = nt * 8 + tig * 2;
        enb[nt][0] = sLB[j0];
        enb[nt][1] = sLB[j0 + 1];
    }

    float p0 = 0.f, p1 = 0.f;           // row gid / row gid+8
#pragma unroll
    for (int nt = 0; nt < 8; nt++) {
        p0 = fmaf(ex2(acc[nt][0]), enb[nt][0], p0);
        p0 = fmaf(ex2(acc[nt][1]), enb[nt][1], p0);
        p1 = fmaf(ex2(acc[nt][2]), enb[nt][0], p1);
        p1 = fmaf(ex2(acc[nt][3]), enb[nt][1], p1);
    }

    float tsum = p0 * sLA[mbase + gid] + p1 * sLA[mbase + gid + 8];

#pragma unroll
    for (int off = 16; off; off >>= 1)
        tsum += __shfl_xor_sync(0xffffffffu, tsum, off);
    if (lane == 0) wsum[w] = tsum;
    __syncthreads();

    if (tid == 0) {
        double t = 0.0;
#pragma unroll
        for (int x = 0; x < 8; x++) t += (double)wsum[x];
        double wgt = (ti == tj) ? 1.0 : 2.0;
        double sgn = ((ti < TB / 2) == (tj < TB / 2)) ? 1.0 : -1.0;
        g_part[bid] = t * wgt * sgn;
        __threadfence();
        s_rank = atomicAdd(&g_count, 1u);
    }
    __syncthreads();

    // ---- last CTA: deterministic fixed-order final reduction ----
    if (s_rank == NBLK - 1) {
        const volatile double* gp = g_part;
        double t = 0.0;
        for (int i = tid; i < NBLK; i += 256) t += gp[i];
        sred[tid] = t;
        __syncthreads();
#pragma unroll
        for (int off = 128; off; off >>= 1) {
            if (tid < off) sred[tid] += sred[tid + off];
            __syncthreads();
        }
        if (tid == 0) out[0] = (float)(sred[0] / 67108864.0);   // / n^2
    }
}

// ---------------------------------------------------------------------------
extern "C" void kernel_launch(void* const* d_in, const int* in_sizes, int n_in,
                              void* d_out, int out_size) {
    const float* src = (const float*)d_in[0];
    const float* tgt = (const float*)d_in[1];

    const int smem_bytes = ATILEB + BTILEB;     // 21504 B
    cudaFuncSetAttribute(pair_kernel, cudaFuncAttributeMaxDynamicSharedMemorySize,
                         smem_bytes);

    split_kernel<<<NP / 128, 128>>>(src, tgt);
    pair_kernel<<<NBLK, 256, smem_bytes>>>((float*)d_out);
}

// round 14
// speedup vs baseline: 1.2946x; 1.2946x over previous
#include <cuda_runtime.h>
#include <cuda_fp16.h>
#include <math.h>
#include <stdint.h>

// ---------------------------------------------------------------------------
// MMD^2 (RBF, gamma=1), 8192x16 fp32, via mma.sync.m16n8k16 fp16 (sm_100 base).
// Single fused kernel.
//
// Coords scaled by sqrt(2*log2e), split x = hi + lo (fp16) INLINE in the
// tile build (each thread owns one row). K = 48:
//   A chunks [hi | lo | hi], B chunks [hi | hi | lo]
//   => acc = 2*log2e*dot(a,b)  (lo*lo dropped, ~2^-22 rel)
// Epilogue: k = ex2(acc) * ena * enb, ena/enb = exp2(-0.5|x_s|^2) per row.
// CTA = 256 threads, output tile 128x128, warp tile 32m x 64n (L1-optimal).
// Upper-triangle tiles; final fixed-order reduction in the last CTA
// (threadfence-reduction pattern, self-resetting counter for graph replay).
// ---------------------------------------------------------------------------

#define NSRC   8192
#define D      16
#define NP     16384
#define TILE   128
#define TB     (NP / TILE)                 // 128
#define NBLK   (TB * (TB + 1) / 2)         // 8256 triangle tiles
#define SQ2L   1.6986436004918308f         // sqrt(2*log2(e))
#define ROWB   112                         // 96B data + 16B pad (conflict-free)
#define NKC    3                           // K = 48, chunks of 16
#define ATILEB (TILE * ROWB)               // 14336 B per tile side

__device__ double g_part[NBLK];
__device__ unsigned int g_count;           // zero-init; self-reset each launch

// ---------------- helpers ----------------
__device__ __forceinline__ float ex2(float x) {
    float r; asm("ex2.approx.f32 %0, %1;" : "=f"(r) : "f"(x)); return r;
}
__device__ __forceinline__ uint32_t smem_u32(const void* p) {
    uint32_t a;
    asm("{ .reg .u64 t; cvta.to.shared.u64 t, %1; cvt.u32.u64 %0, t; }"
        : "=r"(a) : "l"(p));
    return a;
}
__device__ __forceinline__ void ldsm4(uint32_t* r, uint32_t addr) {
    asm volatile("ldmatrix.sync.aligned.m8n8.x4.shared.b16 {%0,%1,%2,%3}, [%4];"
                 : "=r"(r[0]), "=r"(r[1]), "=r"(r[2]), "=r"(r[3]) : "r"(addr));
}
__device__ __forceinline__ void mma16816(float* c, const uint32_t* a,
                                         uint32_t b0, uint32_t b1) {
    asm volatile("mma.sync.aligned.m16n8k16.row.col.f32.f16.f16.f32 "
                 "{%0,%1,%2,%3}, {%4,%5,%6,%7}, {%8,%9}, {%0,%1,%2,%3};"
                 : "+f"(c[0]), "+f"(c[1]), "+f"(c[2]), "+f"(c[3])
                 : "r"(a[0]), "r"(a[1]), "r"(a[2]), "r"(a[3]), "r"(b0), "r"(b1));
}
__device__ __forceinline__ int tri_row_start(int t) {
    return t * TB - ((t * (t - 1)) >> 1);
}

// ---------------------------------------------------------------------------
// Fused kernel: 128x128 output tile per CTA (256 threads, 8 warps).
// Warp w: rows (w&3)*32 + {0,16}, cols (w>>2)*64 (8 n8-tiles).
// ---------------------------------------------------------------------------
__global__ void __launch_bounds__(256, 2) pair_kernel(const float* __restrict__ src,
                                                      const float* __restrict__ tgt,
                                                      float* __restrict__ out) {
    extern __shared__ __align__(16) char dsm[];
    __shared__ float  sLA[TILE];
    __shared__ float  sLB[TILE];
    __shared__ float  wsum[8];
    __shared__ double sred[256];
    __shared__ unsigned int s_rank;

    const int bid  = blockIdx.x;
    const int tid  = threadIdx.x;
    const int lane = tid & 31;
    const int w    = tid >> 5;

    int ti = (int)((2.0 * TB + 1.0 - sqrt((2.0 * TB + 1.0) * (2.0 * TB + 1.0)
                                          - 8.0 * (double)bid)) * 0.5);
    while (tri_row_start(ti + 1) <= bid) ti++;
    while (tri_row_start(ti) > bid) ti--;
    const int tj = ti + (bid - tri_row_start(ti));

    // ---- tile build with INLINE scale + fp16 hi/lo split + norm ----
    {
        const int  row = tid & 127;
        const bool isA = tid < 128;
        const int  pt  = (isA ? ti : tj) * TILE + row;
        const float* x = (pt < NSRC) ? (src + (size_t)pt * D)
                                     : (tgt + (size_t)(pt - NSRC) * D);
        char* rbase = dsm + (isA ? 0 : ATILEB) + row * ROWB;

        float4 v4[4];
#pragma unroll
        for (int i = 0; i < 4; i++) v4[i] = *(const float4*)(x + 4 * i);
        const float* xr = (const float*)v4;

        uint4 u[4];
        __half2* hi2 = (__half2*)&u[0];   // u[0],u[1] = 16 hi halves
        __half2* lo2 = (__half2*)&u[2];   // u[2],u[3] = 16 lo halves
        float ns = 0.f;
#pragma unroll
        for (int d = 0; d < 8; d++) {
            float v0 = xr[2 * d]     * SQ2L;
            float v1 = xr[2 * d + 1] * SQ2L;
            ns = fmaf(v0, v0, ns);
            ns = fmaf(v1, v1, ns);
            __half h0 = __float2half_rn(v0);
            __half h1 = __float2half_rn(v1);
            hi2[d] = __halves2half2(h0, h1);
            lo2[d] = __halves2half2(__float2half_rn(v0 - __half2float(h0)),
                                    __float2half_rn(v1 - __half2float(h1)));
        }

        // A: [hi hi lo lo hi hi]    B: [hi hi hi hi lo lo]
        const int mapA[6] = {0,1, 2,3, 0,1};
        const int mapB[6] = {0,1, 0,1, 2,3};
#pragma unroll
        for (int c = 0; c < 6; c++) {
            int s = isA ? mapA[c] : mapB[c];
            *(uint4*)(rbase + c * 16) = u[s];
        }
        float e = ex2(-0.5f * ns);
        if (isA) sLA[row] = e; else sLB[row] = e;
    }
    __syncthreads();

    const uint32_t sA = smem_u32(dsm);
    const uint32_t sB = sA + ATILEB;
    const int mbase = (w & 3) * 32;
    const int nbase = (w >> 2) * 64;
    const int gid = lane >> 2;
    const int tig = lane & 3;

    // ---- preload A fragments (3 kc x 2 m-tiles = 24 regs) ----
    const uint32_t aRow   = (uint32_t)(mbase + (lane & 7) + ((lane >> 3) & 1) * 8);
    const uint32_t aAddr0 = sA + aRow * ROWB + ((lane >> 4) & 1) * 16;
    const uint32_t aAddr1 = aAddr0 + 16 * ROWB;
    uint32_t a0[NKC][4], a1[NKC][4];
#pragma unroll
    for (int kc = 0; kc < NKC; kc++) {
        ldsm4(a0[kc], aAddr0 + kc * 32);
        ldsm4(a1[kc], aAddr1 + kc * 32);
    }

    const uint32_t bRowQ = (uint32_t)((lane & 7) + ((lane >> 4) & 1) * 8);
    const uint32_t bColH = ((lane >> 3) & 1) * 16;
    uint32_t bAddr[4];
#pragma unroll
    for (int q = 0; q < 4; q++)
        bAddr[q] = sB + (uint32_t)(nbase + 16 * q + bRowQ) * ROWB + bColH;

    float acc[2][8][4];
#pragma unroll
    for (int mt = 0; mt < 2; mt++)
#pragma unroll
        for (int nt = 0; nt < 8; nt++)
#pragma unroll
            for (int e = 0; e < 4; e++) acc[mt][nt][e] = 0.f;

#pragma unroll
    for (int kc = 0; kc < NKC; kc++) {
        const uint32_t ko = kc * 32;
        uint32_t b[4][4];
#pragma unroll
        for (int q = 0; q < 4; q++) ldsm4(b[q], bAddr[q] + ko);
#pragma unroll
        for (int nt = 0; nt < 8; nt++) {
            const uint32_t b0 = b[nt >> 1][(nt & 1) * 2];
            const uint32_t b1 = b[nt >> 1][(nt & 1) * 2 + 1];
            mma16816(acc[0][nt], a0[kc], b0, b1);
            mma16816(acc[1][nt], a1[kc], b0, b1);
        }
    }

    // ---- epilogue: k = ex2(acc) * ena * enb; sum over tile ----
    float ena[2][2];
#pragma unroll
    for (int mt = 0; mt < 2; mt++)
#pragma unroll
        for (int h = 0; h < 2; h++)
            ena[mt][h] = sLA[mbase + mt * 16 + gid + h * 8];

    float enb[8][2];
#pragma unroll
    for (int nt = 0; nt < 8; nt++) {
        int j0 = nbase + nt * 8 + tig * 2;
        enb[nt][0] = sLB[j0];
        enb[nt][1] = sLB[j0 + 1];
    }

    float p[2][2] = {{0.f, 0.f}, {0.f, 0.f}};
#pragma unroll
    for (int mt = 0; mt < 2; mt++)
#pragma unroll
        for (int nt = 0; nt < 8; nt++)
#pragma unroll
            for (int e = 0; e < 4; e++)
                p[mt][e >> 1] = fmaf(ex2(acc[mt][nt][e]), enb[nt][e & 1],
                                     p[mt][e >> 1]);

    float tsum = 0.f;
#pragma unroll
    for (int mt = 0; mt < 2; mt++)
#pragma unroll
        for (int h = 0; h < 2; h++)
            tsum = fmaf(p[mt][h], ena[mt][h], tsum);

#pragma unroll
    for (int off = 16; off; off >>= 1)
        tsum += __shfl_xor_sync(0xffffffffu, tsum, off);
    if (lane == 0) wsum[w] = tsum;
    __syncthreads();

    if (tid == 0) {
        double t = 0.0;
#pragma unroll
        for (int x = 0; x < 8; x++) t += (double)wsum[x];
        double wgt = (ti == tj) ? 1.0 : 2.0;
        double sgn = ((ti < TB / 2) == (tj < TB / 2)) ? 1.0 : -1.0;
        g_part[bid] = t * wgt * sgn;
        __threadfence();
        s_rank = atomicAdd(&g_count, 1u);
    }
    __syncthreads();

    // ---- last CTA: deterministic fixed-order final reduction ----
    if (s_rank == NBLK - 1) {
        const volatile double* gp = g_part;
        double t = 0.0;
        for (int i = tid; i < NBLK; i += 256) t += gp[i];
        sred[tid] = t;
        __syncthreads();
#pragma unroll
        for (int off = 128; off; off >>= 1) {
            if (tid < off) sred[tid] += sred[tid + off];
            __syncthreads();
        }
        if (tid == 0) {
            out[0] = (float)(sred[0] / 67108864.0);   // / n^2, n = 8192
            g_count = 0u;                             // reset for next replay
        }
    }
}

// ---------------------------------------------------------------------------
extern "C" void kernel_launch(void* const* d_in, const int* in_sizes, int n_in,
                              void* d_out, int out_size) {
    const float* src = (const float*)d_in[0];
    const float* tgt = (const float*)d_in[1];

    const int smem_bytes = 2 * ATILEB;     // 28672 B
    cudaFuncSetAttribute(pair_kernel, cudaFuncAttributeMaxDynamicSharedMemorySize,
                         smem_bytes);

    pair_kernel<<<NBLK, 256, smem_bytes>>>(src, tgt, (float*)d_out);
}